// round 14
// baseline (speedup 1.0000x reference)
#include <cuda_runtime.h>
#include <cuda_bf16.h>
#include <cstdint>

// Problem constants
#define BB 2
#define SS 2048
#define DD 1024
#define HH 16
#define DKK 64
#define MM (BB*SS)      // 4096
#define BHH (BB*HH)     // 32
#define KP  512         // k-pairs per 1024-wide row
#define DKP 32          // dk-pairs per head (64/2)

// Scratch (device globals)
__device__ float g_V[BHH*SS*DKK];                     // [bh][t][dk] fp32 (pre-transpose)
// packed bf16-pair planes
__device__ uint32_t g_Xh[3*MM*KP],  g_Xl[3*MM*KP];    // inputs q,k,v: [which][m][kp]
__device__ uint32_t g_Wth[3*DD*KP], g_Wtl[3*DD*KP];   // W transposed: [which][n][kp]
__device__ uint32_t g_Woh[DD*KP],   g_Wol[DD*KP];     // Wo: [n][kp]
__device__ uint32_t g_Ch[MM*KP],    g_Cl[MM*KP];      // attention out: [m][kp]
__device__ uint32_t g_Qph[BHH*SS*DKP], g_Qpl[BHH*SS*DKP]; // Q pairs (pre-scaled 1/8)
__device__ uint32_t g_Kph[BHH*SS*DKP], g_Kpl[BHH*SS*DKP]; // K pairs
__device__ uint32_t g_Vth[BHH*DKK*(SS/2)], g_Vtl[BHH*DKK*(SS/2)]; // V^T: [bh][dk][tp]

// ---------------------------------------------------------------------------
// helpers
// ---------------------------------------------------------------------------
__device__ __forceinline__ void mma_bf16(float c[4], const uint32_t a[4], const uint32_t b[2]) {
    asm volatile(
        "mma.sync.aligned.m16n8k16.row.col.f32.bf16.bf16.f32 "
        "{%0,%1,%2,%3}, {%4,%5,%6,%7}, {%8,%9}, {%0,%1,%2,%3};\n"
        : "+f"(c[0]), "+f"(c[1]), "+f"(c[2]), "+f"(c[3])
        : "r"(a[0]), "r"(a[1]), "r"(a[2]), "r"(a[3]), "r"(b[0]), "r"(b[1]));
}
__device__ __forceinline__ void split2(float x0, float x1, uint32_t& hi, uint32_t& lo) {
    __nv_bfloat16 h0 = __float2bfloat16(x0);
    __nv_bfloat16 h1 = __float2bfloat16(x1);
    __nv_bfloat16 l0 = __float2bfloat16(x0 - __bfloat162float(h0));
    __nv_bfloat16 l1 = __float2bfloat16(x1 - __bfloat162float(h1));
    hi = (uint32_t)__bfloat16_as_ushort(h0) | ((uint32_t)__bfloat16_as_ushort(h1) << 16);
    lo = (uint32_t)__bfloat16_as_ushort(l0) | ((uint32_t)__bfloat16_as_ushort(l1) << 16);
}
#define CP_ASYNC16(dst32, src) \
    asm volatile("cp.async.cg.shared.global [%0], [%1], 16;\n" :: "r"(dst32), "l"(src) : "memory")
#define CP_COMMIT() asm volatile("cp.async.commit_group;\n" ::: "memory")
#define CP_WAIT0()  asm volatile("cp.async.wait_group 0;\n" ::: "memory")

// ---------------------------------------------------------------------------
// convert kernels (one-shot fp32 -> packed bf16 hi/lo)
// ---------------------------------------------------------------------------
__global__ void convert_x(const float* __restrict__ q, const float* __restrict__ k,
                          const float* __restrict__ v) {
    int idx = blockIdx.x * 256 + threadIdx.x;
    int which = idx / (MM * 256);
    int rem = idx - which * (MM * 256);
    int m = rem >> 8, i = rem & 255;
    const float* X = (which == 0) ? q : (which == 1) ? k : v;
    float4 f = *reinterpret_cast<const float4*>(X + (size_t)m * DD + i * 4);
    uint32_t h0, l0, h1, l1;
    split2(f.x, f.y, h0, l0);
    split2(f.z, f.w, h1, l1);
    size_t o = (size_t)which * MM * KP + (size_t)m * KP + i * 2;
    *reinterpret_cast<uint2*>(&g_Xh[o]) = make_uint2(h0, h1);
    *reinterpret_cast<uint2*>(&g_Xl[o]) = make_uint2(l0, l1);
}

__global__ void convert_w(const float* __restrict__ Wq, const float* __restrict__ Wk,
                          const float* __restrict__ Wv) {
    int idx = blockIdx.x * 256 + threadIdx.x;
    int which = idx / (HH * KP * 16);
    int rem = idx - which * (HH * KP * 16);
    int dk4 = rem & 15;
    int kp = (rem >> 4) & 511;
    int h = rem >> 13;
    const float* W = (which == 0) ? Wq : (which == 1) ? Wk : Wv;
    const float* r0 = W + ((size_t)h * DD + 2 * kp) * DKK + dk4 * 4;
    float4 a = *reinterpret_cast<const float4*>(r0);
    float4 b = *reinterpret_cast<const float4*>(r0 + DKK);
    float ax[4] = {a.x, a.y, a.z, a.w};
    float bx[4] = {b.x, b.y, b.z, b.w};
    #pragma unroll
    for (int e = 0; e < 4; e++) {
        uint32_t hi, lo;
        split2(ax[e], bx[e], hi, lo);
        int n = h * 64 + dk4 * 4 + e;
        size_t o = (size_t)which * DD * KP + (size_t)n * KP + kp;
        g_Wth[o] = hi;
        g_Wtl[o] = lo;
    }
}

__global__ void convert_wo(const float* __restrict__ Wo) {
    int idx = blockIdx.x * 256 + threadIdx.x;
    int n = idx >> 8, i = idx & 255;
    float4 f = *reinterpret_cast<const float4*>(Wo + (size_t)n * DD + i * 4);
    uint32_t h0, l0, h1, l1;
    split2(f.x, f.y, h0, l0);
    split2(f.z, f.w, h1, l1);
    size_t o = (size_t)n * KP + i * 2;
    *reinterpret_cast<uint2*>(&g_Woh[o]) = make_uint2(h0, h1);
    *reinterpret_cast<uint2*>(&g_Wol[o]) = make_uint2(l0, l1);
}

// transpose+split V: [bh][t][dk] fp32 -> [bh][dk][tp] bf16 pairs (pair along t)
// grid (SS/32, BHH), block 256
__global__ void convert_vt() {
    __shared__ float sm[32][65];
    const int bh = blockIdx.y;
    const int t0 = blockIdx.x * 32;
    const int tid = threadIdx.x;
    const float* Vg = g_V + (size_t)bh * SS * DKK;
    #pragma unroll
    for (int r = 0; r < 8; r++) {
        int idx = tid + r * 256;
        int t = idx >> 6, dk = idx & 63;
        sm[t][dk] = Vg[(size_t)(t0 + t) * DKK + dk];
    }
    __syncthreads();
    const int dk = tid >> 2;
    const int pg = tid & 3;
    uint32_t* Vth = g_Vth + (size_t)bh * DKK * (SS/2) + (size_t)dk * (SS/2) + t0/2;
    uint32_t* Vtl = g_Vtl + (size_t)bh * DKK * (SS/2) + (size_t)dk * (SS/2) + t0/2;
    #pragma unroll
    for (int e = 0; e < 4; e++) {
        int p = pg * 4 + e;
        uint32_t hi, lo;
        split2(sm[2*p][dk], sm[2*p+1][dk], hi, lo);
        Vth[p] = hi;
        Vtl[p] = lo;
    }
}

// ---------------------------------------------------------------------------
// GEMM core (bf16x3, cp.async double-buffered), 512-thread variant.
// tile 128x128, 16 warps (4x4), warp tile 32x32 -> 32 acc floats/thread.
// smem: 2 buffers x 4 planes x [128 rows][20 words]
// ---------------------------------------------------------------------------
#define PLANE_W 2560
#define BUF_W   (4*PLANE_W)
#define SMEM_GEMM_BYTES (2*BUF_W*4)

struct GemmPtrs { const uint32_t *Ah, *Al, *Bh, *Bl; };

__device__ __forceinline__ void gemm_issue(uint32_t smem_base, const GemmPtrs& P,
                                           int m0, int n0, int s, int b, int tid) {
    const int kp0 = s * 16;
    #pragma unroll
    for (int r = 0; r < 4; r++) {
        int c = tid + r * 512;
        int plane = c >> 9;
        int cc = c & 511;
        int row = cc >> 2, seg = cc & 3;
        const uint32_t* srcb;
        int grow;
        if (plane == 0)      { srcb = P.Ah; grow = m0 + row; }
        else if (plane == 1) { srcb = P.Al; grow = m0 + row; }
        else if (plane == 2) { srcb = P.Bh; grow = n0 + row; }
        else                 { srcb = P.Bl; grow = n0 + row; }
        const uint32_t* src = srcb + (size_t)grow * KP + kp0 + seg * 4;
        uint32_t dst = smem_base + ((b * BUF_W + plane * PLANE_W + row * 20 + seg * 4) << 2);
        CP_ASYNC16(dst, src);
    }
    CP_COMMIT();
}

__device__ __forceinline__ void gemm_compute(const uint32_t* smw, int b,
                                             int wm, int wn, int g, int tg,
                                             float acc[2][4][4]) {
    const uint32_t* Ah_s = smw + b * BUF_W;
    const uint32_t* Al_s = Ah_s + PLANE_W;
    const uint32_t* Bh_s = Ah_s + 2 * PLANE_W;
    const uint32_t* Bl_s = Ah_s + 3 * PLANE_W;
    #pragma unroll
    for (int kf = 0; kf < 2; kf++) {
        const int kb = kf * 8;
        uint32_t bh[4][2], bl[4][2];
        #pragma unroll
        for (int nf = 0; nf < 4; nf++) {
            int nb = wn * 32 + nf * 8 + g;
            bh[nf][0] = Bh_s[nb*20 + kb+tg]; bh[nf][1] = Bh_s[nb*20 + kb+tg+4];
            bl[nf][0] = Bl_s[nb*20 + kb+tg]; bl[nf][1] = Bl_s[nb*20 + kb+tg+4];
        }
        #pragma unroll
        for (int mf = 0; mf < 2; mf++) {
            int mb = wm * 32 + mf * 16 + g;
            uint32_t ah[4], al[4];
            ah[0] = Ah_s[(mb  )*20 + kb+tg  ]; al[0] = Al_s[(mb  )*20 + kb+tg  ];
            ah[1] = Ah_s[(mb+8)*20 + kb+tg  ]; al[1] = Al_s[(mb+8)*20 + kb+tg  ];
            ah[2] = Ah_s[(mb  )*20 + kb+tg+4]; al[2] = Al_s[(mb  )*20 + kb+tg+4];
            ah[3] = Ah_s[(mb+8)*20 + kb+tg+4]; al[3] = Al_s[(mb+8)*20 + kb+tg+4];
            #pragma unroll
            for (int nf = 0; nf < 4; nf++) {
                mma_bf16(acc[mf][nf], ah, bh[nf]);
                mma_bf16(acc[mf][nf], ah, bl[nf]);
                mma_bf16(acc[mf][nf], al, bh[nf]);
            }
        }
    }
}

// ---------------------------------------------------------------------------
// Kernel: QKV projections. grid (32, 8, 3), block 512.
// Q/K outputs -> pre-split bf16 pairs (Q pre-scaled by 1/8); V -> fp32.
// ---------------------------------------------------------------------------
__global__ __launch_bounds__(512, 2) void gemm_proj_tc(void)
{
    extern __shared__ uint32_t smw[];
    const int which = blockIdx.z;
    GemmPtrs P;
    P.Ah = g_Xh + (size_t)which * MM * KP;
    P.Al = g_Xl + (size_t)which * MM * KP;
    P.Bh = g_Wth + (size_t)which * DD * KP;
    P.Bl = g_Wtl + (size_t)which * DD * KP;

    const int m0 = blockIdx.x * 128;
    const int n0 = blockIdx.y * 128;
    const int tid = threadIdx.x;
    const int wid = tid >> 5, lane = tid & 31;
    const int wm = wid >> 2, wn = wid & 3;
    const int g = lane >> 2, tg = lane & 3;
    const uint32_t smem_base = (uint32_t)__cvta_generic_to_shared(smw);

    float acc[2][4][4] = {};

    gemm_issue(smem_base, P, m0, n0, 0, 0, tid);
    for (int s = 0; s < 32; s++) {
        const int b = s & 1;
        CP_WAIT0();
        __syncthreads();
        if (s + 1 < 32) gemm_issue(smem_base, P, m0, n0, s + 1, b ^ 1, tid);
        gemm_compute(smw, b, wm, wn, g, tg, acc);
        __syncthreads();
    }

    const float scale = (which == 0) ? 0.125f : 1.0f;
    #pragma unroll
    for (int mf = 0; mf < 2; mf++) {
        int r0 = m0 + wm * 32 + mf * 16 + g;
        #pragma unroll
        for (int nf = 0; nf < 4; nf++) {
            int c = n0 + wn * 32 + nf * 8 + 2 * tg;
            int h = c >> 6, dk = c & 63;
            if (which == 2) {
                int b_ = r0 >> 11, sI = r0 & 2047;
                float2 o = make_float2(acc[mf][nf][0], acc[mf][nf][1]);
                *reinterpret_cast<float2*>(&g_V[(((size_t)(b_ * HH + h)) * SS + sI) * DKK + dk]) = o;
                int r1 = r0 + 8;
                b_ = r1 >> 11; sI = r1 & 2047;
                o = make_float2(acc[mf][nf][2], acc[mf][nf][3]);
                *reinterpret_cast<float2*>(&g_V[(((size_t)(b_ * HH + h)) * SS + sI) * DKK + dk]) = o;
            } else {
                uint32_t* Oh = (which == 0) ? g_Qph : g_Kph;
                uint32_t* Ol = (which == 0) ? g_Qpl : g_Kpl;
                {
                    int b_ = r0 >> 11, sI = r0 & 2047;
                    size_t o = (((size_t)(b_ * HH + h)) * SS + sI) * DKP + (dk >> 1);
                    uint32_t hi, lo;
                    split2(acc[mf][nf][0] * scale, acc[mf][nf][1] * scale, hi, lo);
                    Oh[o] = hi; Ol[o] = lo;
                }
                {
                    int r1 = r0 + 8;
                    int b_ = r1 >> 11, sI = r1 & 2047;
                    size_t o = (((size_t)(b_ * HH + h)) * SS + sI) * DKP + (dk >> 1);
                    uint32_t hi, lo;
                    split2(acc[mf][nf][2] * scale, acc[mf][nf][3] * scale, hi, lo);
                    Oh[o] = hi; Ol[o] = lo;
                }
            }
        }
    }
}

// ---------------------------------------------------------------------------
// Kernel: output projection. grid (32, 8), block 512.
// ---------------------------------------------------------------------------
__global__ __launch_bounds__(512, 2) void gemm_out_tc(const float* __restrict__ bo,
                                                      float* __restrict__ out)
{
    extern __shared__ uint32_t smw[];
    GemmPtrs P;
    P.Ah = g_Ch; P.Al = g_Cl; P.Bh = g_Woh; P.Bl = g_Wol;

    const int m0 = blockIdx.x * 128;
    const int n0 = blockIdx.y * 128;
    const int tid = threadIdx.x;
    const int wid = tid >> 5, lane = tid & 31;
    const int wm = wid >> 2, wn = wid & 3;
    const int g = lane >> 2, tg = lane & 3;
    const uint32_t smem_base = (uint32_t)__cvta_generic_to_shared(smw);

    float acc[2][4][4] = {};

    gemm_issue(smem_base, P, m0, n0, 0, 0, tid);
    for (int s = 0; s < 32; s++) {
        const int b = s & 1;
        CP_WAIT0();
        __syncthreads();
        if (s + 1 < 32) gemm_issue(smem_base, P, m0, n0, s + 1, b ^ 1, tid);
        gemm_compute(smw, b, wm, wn, g, tg, acc);
        __syncthreads();
    }

    #pragma unroll
    for (int mf = 0; mf < 2; mf++) {
        int r0 = m0 + wm * 32 + mf * 16 + g;
        #pragma unroll
        for (int nf = 0; nf < 4; nf++) {
            int c = n0 + wn * 32 + nf * 8 + 2 * tg;
            float2 bb = *reinterpret_cast<const float2*>(&bo[c]);
            float2 o0 = make_float2(acc[mf][nf][0] + bb.x, acc[mf][nf][1] + bb.y);
            float2 o1 = make_float2(acc[mf][nf][2] + bb.x, acc[mf][nf][3] + bb.y);
            *reinterpret_cast<float2*>(&out[(size_t)r0 * DD + c]) = o0;
            *reinterpret_cast<float2*>(&out[(size_t)(r0 + 8) * DD + c]) = o1;
        }
    }
}

// ---------------------------------------------------------------------------
// Kernel: tensor-core causal flash attention (validated R12 version).
// grid (32, 32). block 128 = 4 warps, 1x4 m-split.
// smem planes (64 rows x 36 words): 0 Qh,1 Ql,2 Kh,3 Kl,4 Vh,5 Vl,6 Ph,7 Pl
// ---------------------------------------------------------------------------
#define PLW 36
#define APL (64*PLW)
#define SMEM_ATTN_BYTES (8*APL*4)   // 73728

__global__ __launch_bounds__(128) void attn_tc()
{
    extern __shared__ uint32_t smw[];
    const int bh = blockIdx.y;
    const int qi = 31 - blockIdx.x;        // heavy tiles first
    const int i0 = qi * 64;
    const int tid = threadIdx.x;
    const int wid = tid >> 5, lane = tid & 31;
    const int g = lane >> 2, tg = lane & 3;
    const int mb = wid * 16;               // warp's row base within tile
    const uint32_t sb = (uint32_t)__cvta_generic_to_shared(smw);

    const uint32_t* Qh_g = g_Qph + (size_t)bh * SS * DKP;
    const uint32_t* Ql_g = g_Qpl + (size_t)bh * SS * DKP;
    const uint32_t* Kh_g = g_Kph + (size_t)bh * SS * DKP;
    const uint32_t* Kl_g = g_Kpl + (size_t)bh * SS * DKP;
    const uint32_t* Vh_g = g_Vth + (size_t)bh * DKK * (SS/2);
    const uint32_t* Vl_g = g_Vtl + (size_t)bh * DKK * (SS/2);

    // load Q tile (64 rows x 32 pairs) into planes 0/1
    #pragma unroll
    for (int r = 0; r < 4; r++) {
        int c = tid + r * 128;
        int row = c >> 3, seg = c & 7;
        CP_ASYNC16(sb + ((0*APL + row*PLW + seg*4) << 2), Qh_g + (size_t)(i0+row)*DKP + seg*4);
        CP_ASYNC16(sb + ((1*APL + row*PLW + seg*4) << 2), Ql_g + (size_t)(i0+row)*DKP + seg*4);
    }
    CP_COMMIT();

    float mrow[2] = {-1e30f, -1e30f};
    float lsum[2] = {0.f, 0.f};
    float oacc[8][4] = {};

    for (int j = 0; j <= qi; j++) {
        const int j0 = j * 64;
        // load K (planes 2/3) and V^T (planes 4/5)
        #pragma unroll
        for (int r = 0; r < 4; r++) {
            int c = tid + r * 128;
            int row = c >> 3, seg = c & 7;
            CP_ASYNC16(sb + ((2*APL + row*PLW + seg*4) << 2), Kh_g + (size_t)(j0+row)*DKP + seg*4);
            CP_ASYNC16(sb + ((3*APL + row*PLW + seg*4) << 2), Kl_g + (size_t)(j0+row)*DKP + seg*4);
            CP_ASYNC16(sb + ((4*APL + row*PLW + seg*4) << 2), Vh_g + (size_t)row*(SS/2) + j0/2 + seg*4);
            CP_ASYNC16(sb + ((5*APL + row*PLW + seg*4) << 2), Vl_g + (size_t)row*(SS/2) + j0/2 + seg*4);
        }
        CP_COMMIT();
        CP_WAIT0();
        __syncthreads();

        // ---- QK^T (bf16x3): warp computes 16 rows x 64 cols ----
        float acc[8][4] = {};
        {
            const uint32_t* Qh_s = smw + 0*APL;
            const uint32_t* Ql_s = smw + 1*APL;
            const uint32_t* Kh_s = smw + 2*APL;
            const uint32_t* Kl_s = smw + 3*APL;
            #pragma unroll
            for (int kf = 0; kf < 4; kf++) {
                const int kb = kf * 8;
                uint32_t ah[4], al[4];
                ah[0] = Qh_s[(mb+g  )*PLW + kb+tg  ]; al[0] = Ql_s[(mb+g  )*PLW + kb+tg  ];
                ah[1] = Qh_s[(mb+g+8)*PLW + kb+tg  ]; al[1] = Ql_s[(mb+g+8)*PLW + kb+tg  ];
                ah[2] = Qh_s[(mb+g  )*PLW + kb+tg+4]; al[2] = Ql_s[(mb+g  )*PLW + kb+tg+4];
                ah[3] = Qh_s[(mb+g+8)*PLW + kb+tg+4]; al[3] = Ql_s[(mb+g+8)*PLW + kb+tg+4];
                #pragma unroll
                for (int nf = 0; nf < 8; nf++) {
                    int nb = nf * 8 + g;
                    uint32_t bh2[2], bl2[2];
                    bh2[0] = Kh_s[nb*PLW + kb+tg]; bh2[1] = Kh_s[nb*PLW + kb+tg+4];
                    bl2[0] = Kl_s[nb*PLW + kb+tg]; bl2[1] = Kl_s[nb*PLW + kb+tg+4];
                    mma_bf16(acc[nf], ah, bh2);
                    mma_bf16(acc[nf], ah, bl2);
                    mma_bf16(acc[nf], al, bh2);
                }
            }
        }

        // ---- mask + online softmax (full row inside this warp) ----
        const bool diag = (j == qi);
        #pragma unroll
        for (int half = 0; half < 2; half++) {
            const int r = i0 + mb + g + half * 8;
            float mx = -1e30f;
            #pragma unroll
            for (int nf = 0; nf < 8; nf++) {
                #pragma unroll
                for (int e = 0; e < 2; e++) {
                    float sv = acc[nf][half*2+e];
                    if (diag && (j0 + nf*8 + 2*tg + e) > r) {
                        sv = -1e30f;
                        acc[nf][half*2+e] = sv;
                    }
                    mx = fmaxf(mx, sv);
                }
            }
            mx = fmaxf(mx, __shfl_xor_sync(0xffffffffu, mx, 1));
            mx = fmaxf(mx, __shfl_xor_sync(0xffffffffu, mx, 2));
            float mnew = fmaxf(mrow[half], mx);
            float corr = __expf(mrow[half] - mnew);
            mrow[half] = mnew;
            float rs = 0.f;
            #pragma unroll
            for (int nf = 0; nf < 8; nf++) {
                #pragma unroll
                for (int e = 0; e < 2; e++) {
                    float p = __expf(acc[nf][half*2+e] - mnew);
                    acc[nf][half*2+e] = p;
                    rs += p;
                }
            }
            rs += __shfl_xor_sync(0xffffffffu, rs, 1);
            rs += __shfl_xor_sync(0xffffffffu, rs, 2);
            lsum[half] = lsum[half] * corr + rs;
            #pragma unroll
            for (int nf = 0; nf < 8; nf++)
                #pragma unroll
                for (int e = 0; e < 2; e++)
                    oacc[nf][half*2+e] *= corr;
        }

        // ---- split P to bf16 pairs in smem (planes 6/7) ----
        #pragma unroll
        for (int half = 0; half < 2; half++) {
            int rowi = mb + g + half * 8;
            #pragma unroll
            for (int nf = 0; nf < 8; nf++) {
                uint32_t hi, lo;
                split2(acc[nf][half*2], acc[nf][half*2+1], hi, lo);
                int idx = rowi * PLW + nf * 4 + tg;
                smw[6*APL + idx] = hi;
                smw[7*APL + idx] = lo;
            }
        }
        __syncwarp();   // P rows are private to this warp

        // ---- P @ V (bf16x3) ----
        {
            const uint32_t* Ph_s = smw + 6*APL;
            const uint32_t* Pl_s = smw + 7*APL;
            const uint32_t* Vh_s = smw + 4*APL;
            const uint32_t* Vl_s = smw + 5*APL;
            #pragma unroll
            for (int kf = 0; kf < 4; kf++) {
                const int kb = kf * 8;
                uint32_t ph[4], pl[4];
                ph[0] = Ph_s[(mb+g  )*PLW + kb+tg  ]; pl[0] = Pl_s[(mb+g  )*PLW + kb+tg  ];
                ph[1] = Ph_s[(mb+g+8)*PLW + kb+tg  ]; pl[1] = Pl_s[(mb+g+8)*PLW + kb+tg  ];
                ph[2] = Ph_s[(mb+g  )*PLW + kb+tg+4]; pl[2] = Pl_s[(mb+g  )*PLW + kb+tg+4];
                ph[3] = Ph_s[(mb+g+8)*PLW + kb+tg+4]; pl[3] = Pl_s[(mb+g+8)*PLW + kb+tg+4];
                #pragma unroll
                for (int nf = 0; nf < 8; nf++) {
                    int nb = nf * 8 + g;
                    uint32_t vbh[2], vbl[2];
                    vbh[0] = Vh_s[nb*PLW + kb+tg]; vbh[1] = Vh_s[nb*PLW + kb+tg+4];
                    vbl[0] = Vl_s[nb*PLW + kb+tg]; vbl[1] = Vl_s[nb*PLW + kb+tg+4];
                    mma_bf16(oacc[nf], ph, vbh);
                    mma_bf16(oacc[nf], ph, vbl);
                    mma_bf16(oacc[nf], pl, vbh);
                }
            }
        }
        __syncthreads();   // done reading K/V planes before next-iter overwrite
    }

    // ---- epilogue: normalize, split, write Ctx pairs ----
    const int b_ = bh / HH, h = bh % HH;
    const float inv0 = 1.f / lsum[0];
    const float inv1 = 1.f / lsum[1];
    const int r0 = i0 + mb + g;
    #pragma unroll
    for (int nf = 0; nf < 8; nf++) {
        int pidx = h * 32 + nf * 4 + tg;
        {
            size_t o = ((size_t)(b_ * SS + r0)) * KP + pidx;
            uint32_t hi, lo;
            split2(oacc[nf][0] * inv0, oacc[nf][1] * inv0, hi, lo);
            g_Ch[o] = hi; g_Cl[o] = lo;
        }
        {
            size_t o = ((size_t)(b_ * SS + r0 + 8)) * KP + pidx;
            uint32_t hi, lo;
            split2(oacc[nf][2] * inv1, oacc[nf][3] * inv1, hi, lo);
            g_Ch[o] = hi; g_Cl[o] = lo;
        }
    }
}

// ---------------------------------------------------------------------------
extern "C" void kernel_launch(void* const* d_in, const int* in_sizes, int n_in,
                              void* d_out, int out_size)
{
    const float* q  = (const float*)d_in[0];
    const float* k  = (const float*)d_in[1];
    const float* v  = (const float*)d_in[2];
    const float* Wq = (const float*)d_in[3];
    const float* Wk = (const float*)d_in[4];
    const float* Wv = (const float*)d_in[5];
    const float* Wo = (const float*)d_in[6];
    const float* bo = (const float*)d_in[7];
    float* out = (float*)d_out;

    cudaFuncSetAttribute(gemm_proj_tc, cudaFuncAttributeMaxDynamicSharedMemorySize, SMEM_GEMM_BYTES);
    cudaFuncSetAttribute(gemm_out_tc,  cudaFuncAttributeMaxDynamicSharedMemorySize, SMEM_GEMM_BYTES);
    cudaFuncSetAttribute(attn_tc,      cudaFuncAttributeMaxDynamicSharedMemorySize, SMEM_ATTN_BYTES);

    convert_x<<<3 * MM, 256>>>(q, k, v);
    convert_w<<<3 * HH * KP * 16 / 256, 256>>>(Wq, Wk, Wv);
    convert_wo<<<DD, 256>>>(Wo);

    gemm_proj_tc<<<dim3(MM / 128, DD / 128, 3), 512, SMEM_GEMM_BYTES>>>();

    convert_vt<<<dim3(SS / 32, BHH), 256>>>();

    attn_tc<<<dim3(32, BHH), 128, SMEM_ATTN_BYTES>>>();

    gemm_out_tc<<<dim3(MM / 128, DD / 128), 512, SMEM_GEMM_BYTES>>>(bo, out);
}

// round 15
// speedup vs baseline: 1.0676x; 1.0676x over previous
#include <cuda_runtime.h>
#include <cuda_bf16.h>
#include <cstdint>

// Problem constants
#define BB 2
#define SS 2048
#define DD 1024
#define HH 16
#define DKK 64
#define MM (BB*SS)      // 4096
#define BHH (BB*HH)     // 32
#define KP  512         // k-pairs per 1024-wide row
#define DKP 32          // dk-pairs per head (64/2)

// Scratch (device globals)
__device__ float g_V[BHH*SS*DKK];                     // [bh][t][dk] fp32 (pre-transpose)
// packed bf16-pair planes
__device__ uint32_t g_Xh[3*MM*KP],  g_Xl[3*MM*KP];    // inputs q,k,v: [which][m][kp]
__device__ uint32_t g_Wth[3*DD*KP], g_Wtl[3*DD*KP];   // W transposed: [which][n][kp]
__device__ uint32_t g_Woh[DD*KP],   g_Wol[DD*KP];     // Wo: [n][kp]
__device__ uint32_t g_Ch[MM*KP],    g_Cl[MM*KP];      // attention out: [m][kp]
__device__ uint32_t g_Qph[BHH*SS*DKP], g_Qpl[BHH*SS*DKP]; // Q pairs (pre-scaled 1/8)
__device__ uint32_t g_Kph[BHH*SS*DKP], g_Kpl[BHH*SS*DKP]; // K pairs
__device__ uint32_t g_Vth[BHH*DKK*(SS/2)], g_Vtl[BHH*DKK*(SS/2)]; // V^T: [bh][dk][tp]

// ---------------------------------------------------------------------------
// helpers
// ---------------------------------------------------------------------------
__device__ __forceinline__ void mma_bf16(float c[4], const uint32_t a[4], const uint32_t b[2]) {
    asm volatile(
        "mma.sync.aligned.m16n8k16.row.col.f32.bf16.bf16.f32 "
        "{%0,%1,%2,%3}, {%4,%5,%6,%7}, {%8,%9}, {%0,%1,%2,%3};\n"
        : "+f"(c[0]), "+f"(c[1]), "+f"(c[2]), "+f"(c[3])
        : "r"(a[0]), "r"(a[1]), "r"(a[2]), "r"(a[3]), "r"(b[0]), "r"(b[1]));
}
__device__ __forceinline__ void split2(float x0, float x1, uint32_t& hi, uint32_t& lo) {
    __nv_bfloat16 h0 = __float2bfloat16(x0);
    __nv_bfloat16 h1 = __float2bfloat16(x1);
    __nv_bfloat16 l0 = __float2bfloat16(x0 - __bfloat162float(h0));
    __nv_bfloat16 l1 = __float2bfloat16(x1 - __bfloat162float(h1));
    hi = (uint32_t)__bfloat16_as_ushort(h0) | ((uint32_t)__bfloat16_as_ushort(h1) << 16);
    lo = (uint32_t)__bfloat16_as_ushort(l0) | ((uint32_t)__bfloat16_as_ushort(l1) << 16);
}
#define CP_ASYNC16(dst32, src) \
    asm volatile("cp.async.cg.shared.global [%0], [%1], 16;\n" :: "r"(dst32), "l"(src) : "memory")
#define CP_COMMIT() asm volatile("cp.async.commit_group;\n" ::: "memory")
#define CP_WAIT0()  asm volatile("cp.async.wait_group 0;\n" ::: "memory")
#define CP_WAIT1()  asm volatile("cp.async.wait_group 1;\n" ::: "memory")

// ---------------------------------------------------------------------------
// convert kernels (one-shot fp32 -> packed bf16 hi/lo)
// ---------------------------------------------------------------------------
__global__ void convert_x(const float* __restrict__ q, const float* __restrict__ k,
                          const float* __restrict__ v) {
    int idx = blockIdx.x * 256 + threadIdx.x;
    int which = idx / (MM * 256);
    int rem = idx - which * (MM * 256);
    int m = rem >> 8, i = rem & 255;
    const float* X = (which == 0) ? q : (which == 1) ? k : v;
    float4 f = *reinterpret_cast<const float4*>(X + (size_t)m * DD + i * 4);
    uint32_t h0, l0, h1, l1;
    split2(f.x, f.y, h0, l0);
    split2(f.z, f.w, h1, l1);
    size_t o = (size_t)which * MM * KP + (size_t)m * KP + i * 2;
    *reinterpret_cast<uint2*>(&g_Xh[o]) = make_uint2(h0, h1);
    *reinterpret_cast<uint2*>(&g_Xl[o]) = make_uint2(l0, l1);
}

__global__ void convert_w(const float* __restrict__ Wq, const float* __restrict__ Wk,
                          const float* __restrict__ Wv) {
    int idx = blockIdx.x * 256 + threadIdx.x;
    int which = idx / (HH * KP * 16);
    int rem = idx - which * (HH * KP * 16);
    int dk4 = rem & 15;
    int kp = (rem >> 4) & 511;
    int h = rem >> 13;
    const float* W = (which == 0) ? Wq : (which == 1) ? Wk : Wv;
    const float* r0 = W + ((size_t)h * DD + 2 * kp) * DKK + dk4 * 4;
    float4 a = *reinterpret_cast<const float4*>(r0);
    float4 b = *reinterpret_cast<const float4*>(r0 + DKK);
    float ax[4] = {a.x, a.y, a.z, a.w};
    float bx[4] = {b.x, b.y, b.z, b.w};
    #pragma unroll
    for (int e = 0; e < 4; e++) {
        uint32_t hi, lo;
        split2(ax[e], bx[e], hi, lo);
        int n = h * 64 + dk4 * 4 + e;
        size_t o = (size_t)which * DD * KP + (size_t)n * KP + kp;
        g_Wth[o] = hi;
        g_Wtl[o] = lo;
    }
}

__global__ void convert_wo(const float* __restrict__ Wo) {
    int idx = blockIdx.x * 256 + threadIdx.x;
    int n = idx >> 8, i = idx & 255;
    float4 f = *reinterpret_cast<const float4*>(Wo + (size_t)n * DD + i * 4);
    uint32_t h0, l0, h1, l1;
    split2(f.x, f.y, h0, l0);
    split2(f.z, f.w, h1, l1);
    size_t o = (size_t)n * KP + i * 2;
    *reinterpret_cast<uint2*>(&g_Woh[o]) = make_uint2(h0, h1);
    *reinterpret_cast<uint2*>(&g_Wol[o]) = make_uint2(l0, l1);
}

// transpose+split V: [bh][t][dk] fp32 -> [bh][dk][tp] bf16 pairs (pair along t)
// grid (SS/32, BHH), block 256
__global__ void convert_vt() {
    __shared__ float sm[32][65];
    const int bh = blockIdx.y;
    const int t0 = blockIdx.x * 32;
    const int tid = threadIdx.x;
    const float* Vg = g_V + (size_t)bh * SS * DKK;
    #pragma unroll
    for (int r = 0; r < 8; r++) {
        int idx = tid + r * 256;
        int t = idx >> 6, dk = idx & 63;
        sm[t][dk] = Vg[(size_t)(t0 + t) * DKK + dk];
    }
    __syncthreads();
    const int dk = tid >> 2;
    const int pg = tid & 3;
    uint32_t* Vth = g_Vth + (size_t)bh * DKK * (SS/2) + (size_t)dk * (SS/2) + t0/2;
    uint32_t* Vtl = g_Vtl + (size_t)bh * DKK * (SS/2) + (size_t)dk * (SS/2) + t0/2;
    #pragma unroll
    for (int e = 0; e < 4; e++) {
        int p = pg * 4 + e;
        uint32_t hi, lo;
        split2(sm[2*p][dk], sm[2*p+1][dk], hi, lo);
        Vth[p] = hi;
        Vtl[p] = lo;
    }
}

// ---------------------------------------------------------------------------
// GEMM core (bf16x3, cp.async double-buffered) -- validated R10/R12 machinery
// 256 threads, 8 warps (2x4), warp tile 64x32.
// ---------------------------------------------------------------------------
#define PLANE_W 2560
#define BUF_W   (4*PLANE_W)
#define SMEM_GEMM_BYTES (2*BUF_W*4)

struct GemmPtrs { const uint32_t *Ah, *Al, *Bh, *Bl; };

__device__ __forceinline__ void gemm_issue(uint32_t smem_base, const GemmPtrs& P,
                                           int m0, int n0, int s, int b, int tid) {
    const int kp0 = s * 16;
    #pragma unroll
    for (int r = 0; r < 8; r++) {
        int c = tid + r * 256;
        int plane = c >> 9;
        int cc = c & 511;
        int row = cc >> 2, seg = cc & 3;
        const uint32_t* srcb;
        int grow;
        if (plane == 0)      { srcb = P.Ah; grow = m0 + row; }
        else if (plane == 1) { srcb = P.Al; grow = m0 + row; }
        else if (plane == 2) { srcb = P.Bh; grow = n0 + row; }
        else                 { srcb = P.Bl; grow = n0 + row; }
        const uint32_t* src = srcb + (size_t)grow * KP + kp0 + seg * 4;
        uint32_t dst = smem_base + ((b * BUF_W + plane * PLANE_W + row * 20 + seg * 4) << 2);
        CP_ASYNC16(dst, src);
    }
    CP_COMMIT();
}

__device__ __forceinline__ void gemm_compute(const uint32_t* smw, int b,
                                             int wm, int wn, int g, int tg,
                                             float acc[4][4][4]) {
    const uint32_t* Ah_s = smw + b * BUF_W;
    const uint32_t* Al_s = Ah_s + PLANE_W;
    const uint32_t* Bh_s = Ah_s + 2 * PLANE_W;
    const uint32_t* Bl_s = Ah_s + 3 * PLANE_W;
    #pragma unroll
    for (int kf = 0; kf < 2; kf++) {
        const int kb = kf * 8;
        uint32_t bh[4][2], bl[4][2];
        #pragma unroll
        for (int nf = 0; nf < 4; nf++) {
            int nb = wn * 32 + nf * 8 + g;
            bh[nf][0] = Bh_s[nb*20 + kb+tg]; bh[nf][1] = Bh_s[nb*20 + kb+tg+4];
            bl[nf][0] = Bl_s[nb*20 + kb+tg]; bl[nf][1] = Bl_s[nb*20 + kb+tg+4];
        }
        #pragma unroll
        for (int mf = 0; mf < 4; mf++) {
            int mb = wm * 64 + mf * 16 + g;
            uint32_t ah[4], al[4];
            ah[0] = Ah_s[(mb  )*20 + kb+tg  ]; al[0] = Al_s[(mb  )*20 + kb+tg  ];
            ah[1] = Ah_s[(mb+8)*20 + kb+tg  ]; al[1] = Al_s[(mb+8)*20 + kb+tg  ];
            ah[2] = Ah_s[(mb  )*20 + kb+tg+4]; al[2] = Al_s[(mb  )*20 + kb+tg+4];
            ah[3] = Ah_s[(mb+8)*20 + kb+tg+4]; al[3] = Al_s[(mb+8)*20 + kb+tg+4];
            #pragma unroll
            for (int nf = 0; nf < 4; nf++) {
                mma_bf16(acc[mf][nf], ah, bh[nf]);
                mma_bf16(acc[mf][nf], ah, bl[nf]);
                mma_bf16(acc[mf][nf], al, bh[nf]);
            }
        }
    }
}

// ---------------------------------------------------------------------------
// Kernel: QKV projections. grid (32, 8, 3), block 256.  (validated R12)
// ---------------------------------------------------------------------------
__global__ __launch_bounds__(256, 2) void gemm_proj_tc(void)
{
    extern __shared__ uint32_t smw[];
    const int which = blockIdx.z;
    GemmPtrs P;
    P.Ah = g_Xh + (size_t)which * MM * KP;
    P.Al = g_Xl + (size_t)which * MM * KP;
    P.Bh = g_Wth + (size_t)which * DD * KP;
    P.Bl = g_Wtl + (size_t)which * DD * KP;

    const int m0 = blockIdx.x * 128;
    const int n0 = blockIdx.y * 128;
    const int tid = threadIdx.x;
    const int wid = tid >> 5, lane = tid & 31;
    const int wm = wid >> 2, wn = wid & 3;
    const int g = lane >> 2, tg = lane & 3;
    const uint32_t smem_base = (uint32_t)__cvta_generic_to_shared(smw);

    float acc[4][4][4] = {};

    gemm_issue(smem_base, P, m0, n0, 0, 0, tid);
    for (int s = 0; s < 32; s++) {
        const int b = s & 1;
        CP_WAIT0();
        __syncthreads();
        if (s + 1 < 32) gemm_issue(smem_base, P, m0, n0, s + 1, b ^ 1, tid);
        gemm_compute(smw, b, wm, wn, g, tg, acc);
        __syncthreads();
    }

    const float scale = (which == 0) ? 0.125f : 1.0f;
    #pragma unroll
    for (int mf = 0; mf < 4; mf++) {
        int r0 = m0 + wm * 64 + mf * 16 + g;
        #pragma unroll
        for (int nf = 0; nf < 4; nf++) {
            int c = n0 + wn * 32 + nf * 8 + 2 * tg;
            int h = c >> 6, dk = c & 63;
            if (which == 2) {
                int b_ = r0 >> 11, sI = r0 & 2047;
                float2 o = make_float2(acc[mf][nf][0], acc[mf][nf][1]);
                *reinterpret_cast<float2*>(&g_V[(((size_t)(b_ * HH + h)) * SS + sI) * DKK + dk]) = o;
                int r1 = r0 + 8;
                b_ = r1 >> 11; sI = r1 & 2047;
                o = make_float2(acc[mf][nf][2], acc[mf][nf][3]);
                *reinterpret_cast<float2*>(&g_V[(((size_t)(b_ * HH + h)) * SS + sI) * DKK + dk]) = o;
            } else {
                uint32_t* Oh = (which == 0) ? g_Qph : g_Kph;
                uint32_t* Ol = (which == 0) ? g_Qpl : g_Kpl;
                {
                    int b_ = r0 >> 11, sI = r0 & 2047;
                    size_t o = (((size_t)(b_ * HH + h)) * SS + sI) * DKP + (dk >> 1);
                    uint32_t hi, lo;
                    split2(acc[mf][nf][0] * scale, acc[mf][nf][1] * scale, hi, lo);
                    Oh[o] = hi; Ol[o] = lo;
                }
                {
                    int r1 = r0 + 8;
                    int b_ = r1 >> 11, sI = r1 & 2047;
                    size_t o = (((size_t)(b_ * HH + h)) * SS + sI) * DKP + (dk >> 1);
                    uint32_t hi, lo;
                    split2(acc[mf][nf][2] * scale, acc[mf][nf][3] * scale, hi, lo);
                    Oh[o] = hi; Ol[o] = lo;
                }
            }
        }
    }
}

// ---------------------------------------------------------------------------
// Kernel: output projection. grid (32, 8), block 256.  (validated R12)
// ---------------------------------------------------------------------------
__global__ __launch_bounds__(256, 2) void gemm_out_tc(const float* __restrict__ bo,
                                                      float* __restrict__ out)
{
    extern __shared__ uint32_t smw[];
    GemmPtrs P;
    P.Ah = g_Ch; P.Al = g_Cl; P.Bh = g_Woh; P.Bl = g_Wol;

    const int m0 = blockIdx.x * 128;
    const int n0 = blockIdx.y * 128;
    const int tid = threadIdx.x;
    const int wid = tid >> 5, lane = tid & 31;
    const int wm = wid >> 2, wn = wid & 3;
    const int g = lane >> 2, tg = lane & 3;
    const uint32_t smem_base = (uint32_t)__cvta_generic_to_shared(smw);

    float acc[4][4][4] = {};

    gemm_issue(smem_base, P, m0, n0, 0, 0, tid);
    for (int s = 0; s < 32; s++) {
        const int b = s & 1;
        CP_WAIT0();
        __syncthreads();
        if (s + 1 < 32) gemm_issue(smem_base, P, m0, n0, s + 1, b ^ 1, tid);
        gemm_compute(smw, b, wm, wn, g, tg, acc);
        __syncthreads();
    }

    #pragma unroll
    for (int mf = 0; mf < 4; mf++) {
        int r0 = m0 + wm * 64 + mf * 16 + g;
        #pragma unroll
        for (int nf = 0; nf < 4; nf++) {
            int c = n0 + wn * 32 + nf * 8 + 2 * tg;
            float2 bb = *reinterpret_cast<const float2*>(&bo[c]);
            float2 o0 = make_float2(acc[mf][nf][0] + bb.x, acc[mf][nf][1] + bb.y);
            float2 o1 = make_float2(acc[mf][nf][2] + bb.x, acc[mf][nf][3] + bb.y);
            *reinterpret_cast<float2*>(&out[(size_t)r0 * DD + c]) = o0;
            *reinterpret_cast<float2*>(&out[(size_t)(r0 + 8) * DD + c]) = o1;
        }
    }
}

// ---------------------------------------------------------------------------
// Kernel: tensor-core causal flash attention, K/V DOUBLE-BUFFERED.
// grid (32, 32). block 128 = 4 warps, 1x4 m-split (validated R12 layout).
// smem planes (64 rows x 36 words):
//   0 Qh, 1 Ql, 6 Ph, 7 Pl
//   buf0: 2 Kh, 3 Kl, 4 Vh, 5 Vl       buf1: 8 Kh, 9 Kl, 10 Vh, 11 Vl
// ---------------------------------------------------------------------------
#define PLW 36
#define APL (64*PLW)
#define SMEM_ATTN_BYTES (12*APL*4)   // 110592

__device__ __forceinline__ void attn_issue_kv(uint32_t sb, int buf, int j0, int tid,
                                              const uint32_t* Kh_g, const uint32_t* Kl_g,
                                              const uint32_t* Vh_g, const uint32_t* Vl_g) {
    const int base = (buf ? 8 : 2);
    #pragma unroll
    for (int r = 0; r < 4; r++) {
        int c = tid + r * 128;
        int row = c >> 3, seg = c & 7;
        CP_ASYNC16(sb + (((base+0)*APL + row*PLW + seg*4) << 2), Kh_g + (size_t)(j0+row)*DKP + seg*4);
        CP_ASYNC16(sb + (((base+1)*APL + row*PLW + seg*4) << 2), Kl_g + (size_t)(j0+row)*DKP + seg*4);
        CP_ASYNC16(sb + (((base+2)*APL + row*PLW + seg*4) << 2), Vh_g + (size_t)row*(SS/2) + j0/2 + seg*4);
        CP_ASYNC16(sb + (((base+3)*APL + row*PLW + seg*4) << 2), Vl_g + (size_t)row*(SS/2) + j0/2 + seg*4);
    }
    CP_COMMIT();
}

__global__ __launch_bounds__(128) void attn_tc()
{
    extern __shared__ uint32_t smw[];
    const int bh = blockIdx.y;
    const int qi = 31 - blockIdx.x;        // heavy tiles first
    const int i0 = qi * 64;
    const int tid = threadIdx.x;
    const int wid = tid >> 5, lane = tid & 31;
    const int g = lane >> 2, tg = lane & 3;
    const int mb = wid * 16;               // warp's row base within tile
    const uint32_t sb = (uint32_t)__cvta_generic_to_shared(smw);

    const uint32_t* Qh_g = g_Qph + (size_t)bh * SS * DKP;
    const uint32_t* Ql_g = g_Qpl + (size_t)bh * SS * DKP;
    const uint32_t* Kh_g = g_Kph + (size_t)bh * SS * DKP;
    const uint32_t* Kl_g = g_Kpl + (size_t)bh * SS * DKP;
    const uint32_t* Vh_g = g_Vth + (size_t)bh * DKK * (SS/2);
    const uint32_t* Vl_g = g_Vtl + (size_t)bh * DKK * (SS/2);

    // prologue: group 0 = Q tile + KV tile 0 (into buf0)
    #pragma unroll
    for (int r = 0; r < 4; r++) {
        int c = tid + r * 128;
        int row = c >> 3, seg = c & 7;
        CP_ASYNC16(sb + ((0*APL + row*PLW + seg*4) << 2), Qh_g + (size_t)(i0+row)*DKP + seg*4);
        CP_ASYNC16(sb + ((1*APL + row*PLW + seg*4) << 2), Ql_g + (size_t)(i0+row)*DKP + seg*4);
    }
    attn_issue_kv(sb, 0, 0, tid, Kh_g, Kl_g, Vh_g, Vl_g);   // commits group 0

    float mrow[2] = {-1e30f, -1e30f};
    float lsum[2] = {0.f, 0.f};
    float oacc[8][4] = {};

    for (int j = 0; j <= qi; j++) {
        const int buf = j & 1;
        const int j0 = j * 64;
        const int base = (buf ? 8 : 2);

        // overlap: issue KV j+1 into other buffer, then wait for KV j
        if (j < qi) {
            attn_issue_kv(sb, buf ^ 1, j0 + 64, tid, Kh_g, Kl_g, Vh_g, Vl_g);
            CP_WAIT1();
        } else {
            CP_WAIT0();
        }
        __syncthreads();

        // ---- QK^T (bf16x3): warp computes 16 rows x 64 cols ----
        float acc[8][4] = {};
        {
            const uint32_t* Qh_s = smw + 0*APL;
            const uint32_t* Ql_s = smw + 1*APL;
            const uint32_t* Kh_s = smw + (base+0)*APL;
            const uint32_t* Kl_s = smw + (base+1)*APL;
            #pragma unroll
            for (int kf = 0; kf < 4; kf++) {
                const int kb = kf * 8;
                uint32_t ah[4], al[4];
                ah[0] = Qh_s[(mb+g  )*PLW + kb+tg  ]; al[0] = Ql_s[(mb+g  )*PLW + kb+tg  ];
                ah[1] = Qh_s[(mb+g+8)*PLW + kb+tg  ]; al[1] = Ql_s[(mb+g+8)*PLW + kb+tg  ];
                ah[2] = Qh_s[(mb+g  )*PLW + kb+tg+4]; al[2] = Ql_s[(mb+g  )*PLW + kb+tg+4];
                ah[3] = Qh_s[(mb+g+8)*PLW + kb+tg+4]; al[3] = Ql_s[(mb+g+8)*PLW + kb+tg+4];
                #pragma unroll
                for (int nf = 0; nf < 8; nf++) {
                    int nb = nf * 8 + g;
                    uint32_t bh2[2], bl2[2];
                    bh2[0] = Kh_s[nb*PLW + kb+tg]; bh2[1] = Kh_s[nb*PLW + kb+tg+4];
                    bl2[0] = Kl_s[nb*PLW + kb+tg]; bl2[1] = Kl_s[nb*PLW + kb+tg+4];
                    mma_bf16(acc[nf], ah, bh2);
                    mma_bf16(acc[nf], ah, bl2);
                    mma_bf16(acc[nf], al, bh2);
                }
            }
        }

        // ---- mask + online softmax (full row inside this warp) ----
        const bool diag = (j == qi);
        #pragma unroll
        for (int half = 0; half < 2; half++) {
            const int r = i0 + mb + g + half * 8;
            float mx = -1e30f;
            #pragma unroll
            for (int nf = 0; nf < 8; nf++) {
                #pragma unroll
                for (int e = 0; e < 2; e++) {
                    float sv = acc[nf][half*2+e];
                    if (diag && (j0 + nf*8 + 2*tg + e) > r) {
                        sv = -1e30f;
                        acc[nf][half*2+e] = sv;
                    }
                    mx = fmaxf(mx, sv);
                }
            }
            mx = fmaxf(mx, __shfl_xor_sync(0xffffffffu, mx, 1));
            mx = fmaxf(mx, __shfl_xor_sync(0xffffffffu, mx, 2));
            float mnew = fmaxf(mrow[half], mx);
            float corr = __expf(mrow[half] - mnew);
            mrow[half] = mnew;
            float rs = 0.f;
            #pragma unroll
            for (int nf = 0; nf < 8; nf++) {
                #pragma unroll
                for (int e = 0; e < 2; e++) {
                    float p = __expf(acc[nf][half*2+e] - mnew);
                    acc[nf][half*2+e] = p;
                    rs += p;
                }
            }
            rs += __shfl_xor_sync(0xffffffffu, rs, 1);
            rs += __shfl_xor_sync(0xffffffffu, rs, 2);
            lsum[half] = lsum[half] * corr + rs;
            #pragma unroll
            for (int nf = 0; nf < 8; nf++)
                #pragma unroll
                for (int e = 0; e < 2; e++)
                    oacc[nf][half*2+e] *= corr;
        }

        // ---- split P to bf16 pairs in smem (planes 6/7) ----
        #pragma unroll
        for (int half = 0; half < 2; half++) {
            int rowi = mb + g + half * 8;
            #pragma unroll
            for (int nf = 0; nf < 8; nf++) {
                uint32_t hi, lo;
                split2(acc[nf][half*2], acc[nf][half*2+1], hi, lo);
                int idx = rowi * PLW + nf * 4 + tg;
                smw[6*APL + idx] = hi;
                smw[7*APL + idx] = lo;
            }
        }
        __syncwarp();   // P rows are private to this warp

        // ---- P @ V (bf16x3) ----
        {
            const uint32_t* Ph_s = smw + 6*APL;
            const uint32_t* Pl_s = smw + 7*APL;
            const uint32_t* Vh_s = smw + (base+2)*APL;
            const uint32_t* Vl_s = smw + (base+3)*APL;
            #pragma unroll
            for (int kf = 0; kf < 4; kf++) {
                const int kb = kf * 8;
                uint32_t ph[4], pl[4];
                ph[0] = Ph_s[(mb+g  )*PLW + kb+tg  ]; pl[0] = Pl_s[(mb+g  )*PLW + kb+tg  ];
                ph[1] = Ph_s[(mb+g+8)*PLW + kb+tg  ]; pl[1] = Pl_s[(mb+g+8)*PLW + kb+tg  ];
                ph[2] = Ph_s[(mb+g  )*PLW + kb+tg+4]; pl[2] = Pl_s[(mb+g  )*PLW + kb+tg+4];
                ph[3] = Ph_s[(mb+g+8)*PLW + kb+tg+4]; pl[3] = Pl_s[(mb+g+8)*PLW + kb+tg+4];
                #pragma unroll
                for (int nf = 0; nf < 8; nf++) {
                    int nb = nf * 8 + g;
                    uint32_t vbh[2], vbl[2];
                    vbh[0] = Vh_s[nb*PLW + kb+tg]; vbh[1] = Vh_s[nb*PLW + kb+tg+4];
                    vbl[0] = Vl_s[nb*PLW + kb+tg]; vbl[1] = Vl_s[nb*PLW + kb+tg+4];
                    mma_bf16(oacc[nf], ph, vbh);
                    mma_bf16(oacc[nf], ph, vbl);
                    mma_bf16(oacc[nf], pl, vbh);
                }
            }
        }
        __syncthreads();   // all warps done with buf before it is re-issued (j+2)
    }

    // ---- epilogue: normalize, split, write Ctx pairs ----
    const int b_ = bh / HH, h = bh % HH;
    const float inv0 = 1.f / lsum[0];
    const float inv1 = 1.f / lsum[1];
    const int r0 = i0 + mb + g;
    #pragma unroll
    for (int nf = 0; nf < 8; nf++) {
        int pidx = h * 32 + nf * 4 + tg;
        {
            size_t o = ((size_t)(b_ * SS + r0)) * KP + pidx;
            uint32_t hi, lo;
            split2(oacc[nf][0] * inv0, oacc[nf][1] * inv0, hi, lo);
            g_Ch[o] = hi; g_Cl[o] = lo;
        }
        {
            size_t o = ((size_t)(b_ * SS + r0 + 8)) * KP + pidx;
            uint32_t hi, lo;
            split2(oacc[nf][2] * inv1, oacc[nf][3] * inv1, hi, lo);
            g_Ch[o] = hi; g_Cl[o] = lo;
        }
    }
}

// ---------------------------------------------------------------------------
extern "C" void kernel_launch(void* const* d_in, const int* in_sizes, int n_in,
                              void* d_out, int out_size)
{
    const float* q  = (const float*)d_in[0];
    const float* k  = (const float*)d_in[1];
    const float* v  = (const float*)d_in[2];
    const float* Wq = (const float*)d_in[3];
    const float* Wk = (const float*)d_in[4];
    const float* Wv = (const float*)d_in[5];
    const float* Wo = (const float*)d_in[6];
    const float* bo = (const float*)d_in[7];
    float* out = (float*)d_out;

    cudaFuncSetAttribute(gemm_proj_tc, cudaFuncAttributeMaxDynamicSharedMemorySize, SMEM_GEMM_BYTES);
    cudaFuncSetAttribute(gemm_out_tc,  cudaFuncAttributeMaxDynamicSharedMemorySize, SMEM_GEMM_BYTES);
    cudaFuncSetAttribute(attn_tc,      cudaFuncAttributeMaxDynamicSharedMemorySize, SMEM_ATTN_BYTES);

    convert_x<<<3 * MM, 256>>>(q, k, v);
    convert_w<<<3 * HH * KP * 16 / 256, 256>>>(Wq, Wk, Wv);
    convert_wo<<<DD, 256>>>(Wo);

    gemm_proj_tc<<<dim3(MM / 128, DD / 128, 3), 256, SMEM_GEMM_BYTES>>>();

    convert_vt<<<dim3(SS / 32, BHH), 256>>>();

    attn_tc<<<dim3(32, BHH), 128, SMEM_ATTN_BYTES>>>();

    gemm_out_tc<<<dim3(MM / 128, DD / 128), 256, SMEM_GEMM_BYTES>>>(bo, out);
}